// round 17
// baseline (speedup 1.0000x reference)
#include <cuda_runtime.h>
#include <math.h>

// ---------------------------------------------------------------------------
// Problem constants
// ---------------------------------------------------------------------------
#define B_     8
#define N_     2048
#define M_     32768
#define QD_    512
#define DR_    256
#define D_     512
#define H_     8
#define DH_    64
#define INNER_ 512
#define TOPK_  8
#define SCALE_ 0.125f

#define DIST_BLOCKS 128
#define NCAND (DIST_BLOCKS * TOPK_)   // 1024
#define STR 68

// ---------------------------------------------------------------------------
// Scratch
// ---------------------------------------------------------------------------
__device__ float g_e0[B_ * DR_];
__device__ float g_cand_d2[B_ * NCAND];
__device__ int   g_cand_idx[B_ * NCAND];
__device__ int   g_topk_idx[B_ * TOPK_];
__device__ float g_WqT[QD_ * INNER_];     // WqT[i][p] = Wq[p][i]
__device__ float g_kappa[B_ * QD_ * 64];  // [b][p][c], c=j*8+h (SCALE folded)
__device__ float g_vw[B_ * 64 * INNER_];  // [b][c][o]
__device__ unsigned int g_done[B_];       // per-batch scan counter

// ---------------------------------------------------------------------------
// helpers
// ---------------------------------------------------------------------------
__device__ __forceinline__ unsigned long long splat2(float f) {
    unsigned long long r;
    asm("mov.b64 %0, {%1, %1};" : "=l"(r) : "f"(f));
    return r;
}
__device__ __forceinline__ void fma2(unsigned long long& d,
                                     unsigned long long a,
                                     unsigned long long b) {
    asm("fma.rn.f32x2 %0, %1, %2, %0;" : "+l"(d) : "l"(a), "l"(b));
}
__device__ __forceinline__ float2 unpack2(unsigned long long v) {
    float2 r;
    asm("mov.b64 {%0, %1}, %2;" : "=f"(r.x), "=f"(r.y) : "l"(v));
    return r;
}
__device__ __forceinline__ unsigned long long u64min(unsigned long long a,
                                                     unsigned long long b) {
    return a < b ? a : b;
}

// ---------------------------------------------------------------------------
// Kernel 0: transpose Wq -> g_WqT  (R12)
// ---------------------------------------------------------------------------
__global__ void transpose512(const float* __restrict__ Wq) {
    __shared__ float tile[32][33];
    int bx = blockIdx.x * 32, by = blockIdx.y * 32;
    int tx = threadIdx.x & 31, ty = threadIdx.x >> 5;
#pragma unroll
    for (int r = ty; r < 32; r += 8)
        tile[r][tx] = Wq[(by + r) * 512 + bx + tx];
    __syncthreads();
#pragma unroll
    for (int r = ty; r < 32; r += 8)
        g_WqT[(bx + r) * 512 + by + tx] = tile[tx][r];
}

// ---------------------------------------------------------------------------
// Kernel 1: e0  (R12)
// ---------------------------------------------------------------------------
__global__ void e0_kernel(const float* __restrict__ x,
                          const float* __restrict__ Wq,
                          const float* __restrict__ We) {
    int b = blockIdx.x;
    int tid = threadIdx.x;  // 512
    __shared__ float xs[QD_];
    __shared__ float q0[QD_];
    __shared__ float part[512];

    xs[tid] = x[(long)b * N_ * QD_ + tid];
    __syncthreads();

    {
        float acc = 0.f;
#pragma unroll 16
        for (int c = 0; c < QD_; c++)
            acc += xs[c] * Wq[c * INNER_ + tid];
        q0[tid] = acc;
    }
    __syncthreads();

    {
        int half = tid >> 8;
        int o = tid & 255;
        int c0 = half * 256;
        float acc = 0.f;
#pragma unroll 16
        for (int c = 0; c < 256; c++)
            acc += q0[c0 + c] * We[(c0 + c) * DR_ + o];
        part[tid] = acc;
    }
    __syncthreads();
    if (tid < DR_)
        g_e0[b * DR_ + tid] = part[tid] + part[tid + 256];
}

// ---------------------------------------------------------------------------
// Kernel 2: distance scan + local top-8 + LAST-BLOCK merge (R12)
// ---------------------------------------------------------------------------
__global__ void dist_topk_kernel(const float* __restrict__ ctx) {
    int b = blockIdx.y;
    int chunk = blockIdx.x;
    int tid = threadIdx.x;
    int warp = tid >> 5, lane = tid & 31;

    __shared__ float es[DR_];
    __shared__ float s_d2[8][TOPK_];
    __shared__ int   s_ix[8][TOPK_];
    __shared__ int   s_last;

    if (tid < DR_) es[tid] = g_e0[b * DR_ + tid];
    __syncthreads();

    const float4* e4 = (const float4*)es;
    float4 ea = e4[lane];
    float4 eb = e4[lane + 32];

    float best[TOPK_];
    int   bidx[TOPK_];
#pragma unroll
    for (int i = 0; i < TOPK_; i++) { best[i] = 3.0e38f; bidx[i] = -1; }

    int row0 = chunk * 256 + warp * 32;
#pragma unroll 2
    for (int r = 0; r < 32; r++) {
        int row = row0 + r;
        const float4* crow = (const float4*)(ctx + ((long)b * M_ + row) * D_);
        float4 ca = crow[lane];
        float4 cb = crow[lane + 32];
        float dx, d2 = 0.f;
        dx = ca.x - ea.x; d2 += dx * dx;
        dx = ca.y - ea.y; d2 += dx * dx;
        dx = ca.z - ea.z; d2 += dx * dx;
        dx = ca.w - ea.w; d2 += dx * dx;
        dx = cb.x - eb.x; d2 += dx * dx;
        dx = cb.y - eb.y; d2 += dx * dx;
        dx = cb.z - eb.z; d2 += dx * dx;
        dx = cb.w - eb.w; d2 += dx * dx;
#pragma unroll
        for (int off = 16; off; off >>= 1)
            d2 += __shfl_down_sync(0xffffffffu, d2, off);
        if (lane == 0 && d2 < best[TOPK_ - 1]) {
            int p = TOPK_ - 1;
            while (p > 0 && best[p - 1] > d2) {
                best[p] = best[p - 1]; bidx[p] = bidx[p - 1]; p--;
            }
            best[p] = d2; bidx[p] = row;
        }
    }

    if (lane == 0) {
#pragma unroll
        for (int i = 0; i < TOPK_; i++) { s_d2[warp][i] = best[i]; s_ix[warp][i] = bidx[i]; }
    }
    __syncthreads();

    if (tid == 0) {
        float fb[TOPK_]; int fi[TOPK_];
#pragma unroll
        for (int i = 0; i < TOPK_; i++) { fb[i] = 3.0e38f; fi[i] = -1; }
        for (int w = 0; w < 8; w++)
            for (int i = 0; i < TOPK_; i++) {
                float d2 = s_d2[w][i];
                if (d2 < fb[TOPK_ - 1]) {
                    int ix = s_ix[w][i];
                    int p = TOPK_ - 1;
                    while (p > 0 && fb[p - 1] > d2) {
                        fb[p] = fb[p - 1]; fi[p] = fi[p - 1]; p--;
                    }
                    fb[p] = d2; fi[p] = ix;
                }
            }
        int off = (b * DIST_BLOCKS + chunk) * TOPK_;
        for (int i = 0; i < TOPK_; i++) { g_cand_d2[off + i] = fb[i]; g_cand_idx[off + i] = fi[i]; }
        __threadfence();
        unsigned int v = atomicAdd(&g_done[b], 1u);
        s_last = (v == DIST_BLOCKS - 1);
    }
    __syncthreads();

    if (!s_last) return;
    __threadfence();  // acquire

    __shared__ unsigned long long warpmin[8];
    __shared__ unsigned long long winner;

    unsigned long long k[4];
    int base = b * NCAND;
#pragma unroll
    for (int s = 0; s < 4; s++) {
        int i = tid + s * 256;
        float d2 = g_cand_d2[base + i];
        int ix = g_cand_idx[base + i];
        k[s] = ((unsigned long long)__float_as_uint(d2) << 32) | (unsigned int)ix;
    }

    for (int sel = 0; sel < TOPK_; sel++) {
        unsigned long long m = u64min(u64min(k[0], k[1]), u64min(k[2], k[3]));
#pragma unroll
        for (int off = 16; off; off >>= 1)
            m = u64min(m, __shfl_down_sync(0xffffffffu, m, off));
        if (lane == 0) warpmin[warp] = m;
        __syncthreads();
        if (tid == 0) {
            unsigned long long w = warpmin[0];
#pragma unroll
            for (int i = 1; i < 8; i++) w = u64min(w, warpmin[i]);
            winner = w;
            g_topk_idx[b * TOPK_ + sel] = (int)(unsigned int)(w & 0xffffffffu);
        }
        __syncthreads();
        unsigned long long w = winner;
#pragma unroll
        for (int s = 0; s < 4; s++)
            if (k[s] == w) k[s] = ~0ULL;
        __syncthreads();
    }
    if (tid == 0) g_done[b] = 0;  // reset for graph replay
}

// ---------------------------------------------------------------------------
// Kernel 3: fused kv + kappa + vw (R16, unchanged)
// ---------------------------------------------------------------------------
__global__ void __launch_bounds__(512)
kvkw2_kernel(const float* __restrict__ ctx,
             const float* __restrict__ Wk,
             const float* __restrict__ Wv,
             const float* __restrict__ Wout) {
    __shared__ float rows[8 * 512];     // [j][0:256)=reps, [256:512)=labels
    __shared__ float part[8 * 64 * 9];  // [(rq*2+kv)][d][j] padded to 9
    __shared__ float kh[8 * 64];        // [j][d]
    __shared__ float vh[8 * 64];        // [j][d]

    int h = blockIdx.x, b = blockIdx.y;
    int tid = threadIdx.x;  // 512

#pragma unroll
    for (int i = 0; i < 8; i++) {
        int f = tid + i * 512;
        int j = f >> 9, idx = f & 511;
        rows[j * 512 + idx] =
            ctx[((long)b * M_ + g_topk_idx[b * 8 + j]) * D_ + idx];
    }
    __syncthreads();

    {
        int d = tid & 63;
        int kv = (tid >> 6) & 1;
        int rq = tid >> 7;
        const float* W = kv ? Wv : Wk;
        int off = kv ? 0 : 256;
        int gcol = h * 64 + d;

        float acc[8];
#pragma unroll
        for (int j = 0; j < 8; j++) acc[j] = 0.f;
#pragma unroll 8
        for (int rr = 0; rr < 64; rr++) {
            int r = rq * 64 + rr;
            float w = W[r * INNER_ + gcol];
#pragma unroll
            for (int j = 0; j < 8; j++)
                acc[j] += rows[j * 512 + off + r] * w;
        }
        int base = ((rq * 2 + kv) * 64 + d) * 9;
#pragma unroll
        for (int j = 0; j < 8; j++) part[base + j] = acc[j];
    }
    __syncthreads();

#pragma unroll
    for (int s = 0; s < 2; s++) {
        int o = tid + s * 512;
        int kv = o >> 9;
        int rem = o & 511;
        int d = rem >> 3, j = rem & 7;
        float sum = 0.f;
#pragma unroll
        for (int rq = 0; rq < 4; rq++)
            sum += part[((rq * 2 + kv) * 64 + d) * 9 + j];
        if (kv == 0) kh[j * 64 + d] = sum;
        else         vh[j * 64 + d] = sum;
    }
    __syncthreads();

    {
        float acc[8];
#pragma unroll
        for (int j = 0; j < 8; j++) acc[j] = 0.f;
#pragma unroll 8
        for (int d = 0; d < 64; d++) {
            float w = g_WqT[(h * 64 + d) * 512 + tid];
#pragma unroll
            for (int j = 0; j < 8; j++) acc[j] += w * kh[j * 64 + d];
        }
        long kbase = ((long)b * 512 + tid) * 64 + h;
#pragma unroll
        for (int j = 0; j < 8; j++) g_kappa[kbase + j * 8] = acc[j] * SCALE_;
    }
    {
        float acc[8];
#pragma unroll
        for (int j = 0; j < 8; j++) acc[j] = 0.f;
#pragma unroll 8
        for (int d = 0; d < 64; d++) {
            float w = Wout[(h * 64 + d) * 512 + tid];
#pragma unroll
            for (int j = 0; j < 8; j++) acc[j] += vh[j * 64 + d] * w;
        }
#pragma unroll
        for (int j = 0; j < 8; j++)
            g_vw[((long)b * 64 + j * 8 + h) * 512 + tid] = acc[j];
    }
}

// ---------------------------------------------------------------------------
// Kernel 4: fused sim + softmax + out. RETILED: 4 tok x 8 cols per thread
// (tx owns cols tx*4..+3 and 32+tx*4..+3 -> conflict-free LDS.128 lanes).
// Per 4-k block: 12 LDS + 16 splat + 64 fma2 (fma ceiling 70% vs 59%).
// grid (16, B), 256 thr, 128-token tile, single wave.
// ---------------------------------------------------------------------------
__global__ void __launch_bounds__(256)
fused_attn(const float* __restrict__ x,
           float* __restrict__ out,
           const float* __restrict__ bout) {
    extern __shared__ float fsm[];
    float* xs = fsm;              // 128*68: x chunk, then attention weights a
    float* ks = fsm + 128 * STR;  // 64*68: kappa chunk, then vw chunk

    int nc = blockIdx.x, b = blockIdx.y;
    int n0 = nc * 128;
    int tid = threadIdx.x;
    int ty = tid >> 3, tx = tid & 7;   // 32 ty x 8 tx
    int tok0 = ty * 4;                 // 4 tokens per thread
    int cA = tx * 4;                   // cols cA..cA+3
    int cB = 32 + tx * 4;              // cols cB..cB+3

    const float* xb = x + ((long)b * N_ + n0) * QD_;
    const float* kb = g_kappa + (long)b * QD_ * 64;

    unsigned long long acc2[4][4];     // [token][pair]: 0,1 -> cA; 2,3 -> cB
#pragma unroll
    for (int t = 0; t < 4; t++)
#pragma unroll
        for (int c = 0; c < 4; c++) acc2[t][c] = 0ULL;

    // ---- phase 1: sim = x @ kappa, K in 8 chunks of 64 ----
    for (int pc = 0; pc < 8; pc++) {
        int p0 = pc * 64;
#pragma unroll
        for (int l = 0; l < 8; l++) {
            int f = tid + l * 256;
            int row = f >> 4, c4 = (f & 15) * 4;
            *(float4*)&xs[row * STR + c4] =
                *(const float4*)(xb + (long)row * QD_ + p0 + c4);
        }
#pragma unroll
        for (int l = 0; l < 4; l++) {
            int f = tid + l * 256;
            int row = f >> 4, c4 = (f & 15) * 4;
            *(float4*)&ks[row * STR + c4] =
                *(const float4*)(kb + (long)(p0 + row) * 64 + c4);
        }
        __syncthreads();

#pragma unroll
        for (int kk4 = 0; kk4 < 64; kk4 += 4) {
            float4 a4[4];
#pragma unroll
            for (int t = 0; t < 4; t++)
                a4[t] = *(const float4*)&xs[(tok0 + t) * STR + kk4];
#pragma unroll
            for (int q = 0; q < 4; q++) {
                ulonglong2 bpA = *(const ulonglong2*)&ks[(kk4 + q) * STR + cA];
                ulonglong2 bpB = *(const ulonglong2*)&ks[(kk4 + q) * STR + cB];
#pragma unroll
                for (int t = 0; t < 4; t++) {
                    unsigned long long av = splat2(((const float*)&a4[t])[q]);
                    fma2(acc2[t][0], av, bpA.x);
                    fma2(acc2[t][1], av, bpA.y);
                    fma2(acc2[t][2], av, bpB.x);
                    fma2(acc2[t][3], av, bpB.y);
                }
            }
        }
        __syncthreads();
    }

    // ---- dump sim into xs[token][c] ----
#pragma unroll
    for (int t = 0; t < 4; t++) {
        float2 p0f = unpack2(acc2[t][0]);
        float2 p1f = unpack2(acc2[t][1]);
        float2 p2f = unpack2(acc2[t][2]);
        float2 p3f = unpack2(acc2[t][3]);
        *(float4*)&xs[(tok0 + t) * STR + cA] =
            make_float4(p0f.x, p0f.y, p1f.x, p1f.y);
        *(float4*)&xs[(tok0 + t) * STR + cB] =
            make_float4(p2f.x, p2f.y, p3f.x, p3f.y);
    }
    __syncthreads();

    // ---- softmax in place over j per (token, head): 1024 tasks ----
#pragma unroll
    for (int s = 0; s < 4; s++) {
        int task = s * 256 + tid;
        int t = task >> 3, h = task & 7;
        float v[8];
#pragma unroll
        for (int j = 0; j < 8; j++) v[j] = xs[t * STR + j * 8 + h];
        float m = v[0];
#pragma unroll
        for (int j = 1; j < 8; j++) m = fmaxf(m, v[j]);
        float e[8], sum = 0.f;
#pragma unroll
        for (int j = 0; j < 8; j++) { e[j] = __expf(v[j] - m); sum += e[j]; }
        float inv = 1.f / sum;
#pragma unroll
        for (int j = 0; j < 8; j++) xs[t * STR + j * 8 + h] = e[j] * inv;
    }
    __syncthreads();

    // ---- phase 3: out = a @ vw + bias, 8 o-chunks of 64 ----
    const float* vwb = g_vw + (long)b * 64 * 512;
    float* ob = out + ((long)b * N_ + n0) * 512;

    for (int oc = 0; oc < 8; oc++) {
        int o0 = oc * 64;
#pragma unroll
        for (int l = 0; l < 4; l++) {
            int f = tid + l * 256;
            int row = f >> 4, c4 = (f & 15) * 4;
            *(float4*)&ks[row * STR + c4] =
                *(const float4*)(vwb + (long)row * 512 + o0 + c4);
        }
#pragma unroll
        for (int t = 0; t < 4; t++)
#pragma unroll
            for (int c = 0; c < 4; c++) acc2[t][c] = 0ULL;
        __syncthreads();

#pragma unroll
        for (int cc4 = 0; cc4 < 64; cc4 += 4) {
            float4 a4[4];
#pragma unroll
            for (int t = 0; t < 4; t++)
                a4[t] = *(const float4*)&xs[(tok0 + t) * STR + cc4];
#pragma unroll
            for (int q = 0; q < 4; q++) {
                ulonglong2 bpA = *(const ulonglong2*)&ks[(cc4 + q) * STR + cA];
                ulonglong2 bpB = *(const ulonglong2*)&ks[(cc4 + q) * STR + cB];
#pragma unroll
                for (int t = 0; t < 4; t++) {
                    unsigned long long av = splat2(((const float*)&a4[t])[q]);
                    fma2(acc2[t][0], av, bpA.x);
                    fma2(acc2[t][1], av, bpA.y);
                    fma2(acc2[t][2], av, bpB.x);
                    fma2(acc2[t][3], av, bpB.y);
                }
            }
        }

        float4 biasA = *(const float4*)(bout + o0 + cA);
        float4 biasB = *(const float4*)(bout + o0 + cB);
#pragma unroll
        for (int t = 0; t < 4; t++) {
            float2 p0f = unpack2(acc2[t][0]);
            float2 p1f = unpack2(acc2[t][1]);
            float2 p2f = unpack2(acc2[t][2]);
            float2 p3f = unpack2(acc2[t][3]);
            float4 rA = make_float4(p0f.x + biasA.x, p0f.y + biasA.y,
                                    p1f.x + biasA.z, p1f.y + biasA.w);
            float4 rB = make_float4(p2f.x + biasB.x, p2f.y + biasB.y,
                                    p3f.x + biasB.z, p3f.y + biasB.w);
            *(float4*)(ob + (long)(tok0 + t) * 512 + o0 + cA) = rA;
            *(float4*)(ob + (long)(tok0 + t) * 512 + o0 + cB) = rB;
        }
        __syncthreads();
    }
}

// ---------------------------------------------------------------------------
// Launch: 5 kernels (R16 structure, fused_attn retiled).
// ---------------------------------------------------------------------------
extern "C" void kernel_launch(void* const* d_in, const int* in_sizes, int n_in,
                              void* d_out, int out_size) {
    const float* x    = (const float*)d_in[0];
    const float* ctx  = (const float*)d_in[1];
    const float* Wq   = (const float*)d_in[2];
    const float* Wk   = (const float*)d_in[3];
    const float* Wv   = (const float*)d_in[4];
    const float* We   = (const float*)d_in[5];
    const float* Wout = (const float*)d_in[6];
    const float* bout = (const float*)d_in[7];
    float* out = (float*)d_out;

    const int FA_SMEM = (128 * STR + 64 * STR) * sizeof(float);  // ~51 KB
    cudaFuncSetAttribute(fused_attn,
                         cudaFuncAttributeMaxDynamicSharedMemorySize, FA_SMEM);

    transpose512<<<dim3(16, 16), 256>>>(Wq);
    e0_kernel<<<B_, 512>>>(x, Wq, We);
    dist_topk_kernel<<<dim3(DIST_BLOCKS, B_), 256>>>(ctx);
    kvkw2_kernel<<<dim3(8, 8), 512>>>(ctx, Wk, Wv, Wout);
    fused_attn<<<dim3(16, B_), 256, FA_SMEM>>>(x, out, bout);
}